// round 14
// baseline (speedup 1.0000x reference)
#include <cuda_runtime.h>
#include <cstdint>

#define N_NODES 50000
#define N_EDGES 800000
#define NFEAT   512
#define H1      256
#define H2      128
#define SCAN_B  256
#define SCAN_NBLK ((N_NODES + SCAN_B - 1) / SCAN_B)   // 196

// ---------------- scratch (device globals; no allocation allowed) ----------
__device__ float g_dinv[N_NODES];
__device__ int   g_cnt [N_NODES];
__device__ int   g_off [N_NODES];
__device__ int   g_cur [N_NODES];
__device__ int   g_csr_src[N_EDGES];
__device__ int   g_blksum[SCAN_NBLK];
__device__ float g_h  [N_NODES * H1];
__device__ float g_agg[N_NODES * H1];
__device__ float g_h2 [N_NODES * H2];

// ---------------- helpers ---------------------------------------------------
__device__ __forceinline__ uint32_t tf32u(float x) {
    float y; asm("cvt.rna.tf32.f32 %0, %1;" : "=f"(y) : "f"(x));
    return __float_as_uint(y);
}
__device__ __forceinline__ void mma_tf32(float c[4], const uint32_t a[4],
                                         const uint32_t b[2]) {
    asm volatile(
        "mma.sync.aligned.m16n8k8.row.col.f32.tf32.tf32.f32 "
        "{%0,%1,%2,%3}, {%4,%5,%6,%7}, {%8,%9}, {%0,%1,%2,%3};"
        : "+f"(c[0]), "+f"(c[1]), "+f"(c[2]), "+f"(c[3])
        : "r"(a[0]), "r"(a[1]), "r"(a[2]), "r"(a[3]), "r"(b[0]), "r"(b[1]));
}
__device__ __forceinline__ void cp_async16(void* smem, const void* gmem, bool valid) {
    uint32_t s = (uint32_t)__cvta_generic_to_shared(smem);
    int sz = valid ? 16 : 0;
    asm volatile("cp.async.cg.shared.global [%0], [%1], 16, %2;"
                 :: "r"(s), "l"(gmem), "r"(sz));
}
#define CP_COMMIT() asm volatile("cp.async.commit_group;")
#define CP_WAIT1()  asm volatile("cp.async.wait_group 1;")
#define CP_WAIT0()  asm volatile("cp.async.wait_group 0;")

// ---------------- CSR build --------------------------------------------------
__global__ void zero_cnt_kernel() {
    int i = blockIdx.x * blockDim.x + threadIdx.x;
    if (i < N_NODES) g_cnt[i] = 0;
}
__global__ void deg_count_kernel(const int* __restrict__ dst) {
    int e = blockIdx.x * blockDim.x + threadIdx.x;
    if (e < N_EDGES) atomicAdd(&g_cnt[dst[e]], 1);
}
__global__ void deg_finalize_kernel() {
    int i = blockIdx.x * blockDim.x + threadIdx.x;
    if (i < N_NODES) g_dinv[i] = rsqrtf((float)g_cnt[i] + 1.0f);  // +1 self-loop
}
__global__ __launch_bounds__(SCAN_B)
void scanA_kernel() {
    __shared__ int sh[SCAN_B / 32];
    int idx = blockIdx.x * SCAN_B + threadIdx.x;
    int v = (idx < N_NODES) ? g_cnt[idx] : 0;
#pragma unroll
    for (int d = 16; d > 0; d >>= 1) v += __shfl_down_sync(~0u, v, d);
    if ((threadIdx.x & 31) == 0) sh[threadIdx.x >> 5] = v;
    __syncthreads();
    if (threadIdx.x < SCAN_B / 32) {
        int s = sh[threadIdx.x];
#pragma unroll
        for (int d = SCAN_B / 64; d > 0; d >>= 1) s += __shfl_down_sync(~0u, s, d);
        if (threadIdx.x == 0) g_blksum[blockIdx.x] = s;
    }
}
__global__ __launch_bounds__(SCAN_B)
void scanB_kernel() {
    __shared__ int sh[SCAN_B];
    int t = threadIdx.x;
    int v = (t < SCAN_NBLK) ? g_blksum[t] : 0;
    sh[t] = v;
    __syncthreads();
    for (int d = 1; d < SCAN_B; d <<= 1) {
        int u = (t >= d) ? sh[t - d] : 0;
        __syncthreads();
        sh[t] += u;
        __syncthreads();
    }
    if (t < SCAN_NBLK) g_blksum[t] = sh[t] - v;   // exclusive
}
__global__ __launch_bounds__(SCAN_B)
void scanC_kernel() {
    __shared__ int sh[SCAN_B];
    int t = threadIdx.x;
    int idx = blockIdx.x * SCAN_B + t;
    int v = (idx < N_NODES) ? g_cnt[idx] : 0;
    sh[t] = v;
    __syncthreads();
    for (int d = 1; d < SCAN_B; d <<= 1) {
        int u = (t >= d) ? sh[t - d] : 0;
        __syncthreads();
        sh[t] += u;
        __syncthreads();
    }
    if (idx < N_NODES) {
        int off = g_blksum[blockIdx.x] + sh[t] - v;
        g_off[idx] = off;
        g_cur[idx] = off;
    }
}
__global__ void fill_kernel(const int* __restrict__ src,
                            const int* __restrict__ dst) {
    int e = blockIdx.x * blockDim.x + threadIdx.x;
    if (e >= N_EDGES) return;
    int pos = atomicAdd(&g_cur[dst[e]], 1);
    g_csr_src[pos] = src[e];
}

// ---------------- tf32 tensor GEMM (cp.async 2-stage pipeline) --------------
// BM=128, BN=128, BK=32; 8 warps, warp tile 64x32.
// fp32 tiles in smem; cvt.rna.tf32 at fragment load (matches JAX rna rounding).
#define AS_LD 36
#define BS_LD 132
struct GemmSmem {
    float As[2][128][AS_LD];
    float Bs[2][32][BS_LD];
};

__global__ __launch_bounds__(256, 2)
void tf32_gemm_kernel(const float* __restrict__ A, const float* __restrict__ B,
                      float* __restrict__ C, int M, int N, int K) {
    extern __shared__ char smem_raw[];
    GemmSmem& sm = *reinterpret_cast<GemmSmem*>(smem_raw);

    int tid  = threadIdx.x;
    int m0   = blockIdx.x * 128;
    int n0   = blockIdx.y * 128;
    int wid  = tid >> 5;
    int lane = tid & 31;
    int wm = (wid & 1) * 64;
    int wn = (wid >> 1) * 32;
    int lq = lane >> 2;
    int lr = lane & 3;

    float c[4][4][4];
#pragma unroll
    for (int i = 0; i < 4; i++)
#pragma unroll
        for (int j = 0; j < 4; j++)
#pragma unroll
            for (int r = 0; r < 4; r++) c[i][j][r] = 0.0f;

    int a_r = tid >> 3;
    int a_c = (tid & 7) * 4;
    int b_r = tid >> 5;
    int b_c = (tid & 31) * 4;

    auto issue_tile = [&](int k0, int buf) {
#pragma unroll
        for (int p = 0; p < 4; p++) {
            int r = a_r + p * 32;
            bool valid = (m0 + r) < M;
            const float* gp = A + (size_t)(valid ? (m0 + r) : 0) * K + k0 + a_c;
            cp_async16(&sm.As[buf][r][a_c], gp, valid);
        }
#pragma unroll
        for (int p = 0; p < 4; p++) {
            int r = b_r + p * 8;
            cp_async16(&sm.Bs[buf][r][b_c], B + (size_t)(k0 + r) * N + n0 + b_c, true);
        }
    };

    const int nk = K / 32;
    issue_tile(0, 0);
    CP_COMMIT();

    for (int it = 0; it < nk; it++) {
        if (it + 1 < nk) {
            issue_tile((it + 1) * 32, (it + 1) & 1);
            CP_COMMIT();
            CP_WAIT1();
        } else {
            CP_WAIT0();
        }
        __syncthreads();

        int buf = it & 1;
#pragma unroll
        for (int kk = 0; kk < 4; kk++) {
            int k = kk * 8;
            uint32_t a[4][4], b[4][2];
#pragma unroll
            for (int i = 0; i < 4; i++) {
                int r = wm + i * 16 + lq;
                a[i][0] = tf32u(sm.As[buf][r    ][k + lr    ]);
                a[i][1] = tf32u(sm.As[buf][r + 8][k + lr    ]);
                a[i][2] = tf32u(sm.As[buf][r    ][k + lr + 4]);
                a[i][3] = tf32u(sm.As[buf][r + 8][k + lr + 4]);
            }
#pragma unroll
            for (int j = 0; j < 4; j++) {
                int cc = wn + j * 8 + lq;
                b[j][0] = tf32u(sm.Bs[buf][k + lr    ][cc]);
                b[j][1] = tf32u(sm.Bs[buf][k + lr + 4][cc]);
            }
#pragma unroll
            for (int i = 0; i < 4; i++)
#pragma unroll
                for (int j = 0; j < 4; j++)
                    mma_tf32(c[i][j], a[i], b[j]);
        }
        __syncthreads();
    }

#pragma unroll
    for (int i = 0; i < 4; i++) {
        int r0 = m0 + wm + i * 16 + lq;
        int r1 = r0 + 8;
#pragma unroll
        for (int j = 0; j < 4; j++) {
            int col = n0 + wn + j * 8 + 2 * lr;
            if (r0 < M)
                *(float2*)(C + (size_t)r0 * N + col) =
                    make_float2(c[i][j][0], c[i][j][1]);
            if (r1 < M)
                *(float2*)(C + (size_t)r1 * N + col) =
                    make_float2(c[i][j][2], c[i][j][3]);
        }
    }
}

// ---------------- CSR gather with lane-batched index prefetch ----------------
// warp per dst node. Edge ids + norms for up to 32 edges fetched with TWO
// coalesced/gathered loads, then broadcast via shfl — removes the serialized
// id->dinv->row dependency chain from the inner loop.
template <int C, bool RELU>
__global__ void gather_kernel(const float* __restrict__ h,
                              float* __restrict__ outp,
                              const float* __restrict__ bias) {
    int node = (blockIdx.x * blockDim.x + threadIdx.x) >> 5;
    int lane = threadIdx.x & 31;
    if (node >= N_NODES) return;
    const int CV = C / 128;            // float4 per lane

    float dd = g_dinv[node];
    float w  = dd * dd;

    float4 acc[CV];
    const float4* hd = (const float4*)(h + (size_t)node * C);
#pragma unroll
    for (int v = 0; v < CV; v++) {
        float4 t = hd[lane + 32 * v];
        acc[v] = make_float4(t.x * w, t.y * w, t.z * w, t.w * w);
    }

    int beg = g_off[node];
    int cnt = g_cnt[node];

    for (int base = 0; base < cnt; base += 32) {
        int take = cnt - base;
        if (take > 32) take = 32;
        // batch-fetch up to 32 edge ids (coalesced) + norms (gathered)
        int   myid   = 0;
        float mynorm = 0.0f;
        if (lane < take) {
            myid   = g_csr_src[beg + base + lane];
            mynorm = g_dinv[myid] * dd;
        }

        int e = 0;
        for (; e + 3 < take; e += 4) {
            int   s0 = __shfl_sync(~0u, myid, e);
            int   s1 = __shfl_sync(~0u, myid, e + 1);
            int   s2 = __shfl_sync(~0u, myid, e + 2);
            int   s3 = __shfl_sync(~0u, myid, e + 3);
            float n0 = __shfl_sync(~0u, mynorm, e);
            float n1 = __shfl_sync(~0u, mynorm, e + 1);
            float n2 = __shfl_sync(~0u, mynorm, e + 2);
            float n3 = __shfl_sync(~0u, mynorm, e + 3);
            const float4* h0 = (const float4*)(h + (size_t)s0 * C);
            const float4* h1 = (const float4*)(h + (size_t)s1 * C);
            const float4* h2 = (const float4*)(h + (size_t)s2 * C);
            const float4* h3 = (const float4*)(h + (size_t)s3 * C);
#pragma unroll
            for (int v = 0; v < CV; v++) {
                int idx = lane + 32 * v;
                float4 t0 = h0[idx], t1 = h1[idx], t2 = h2[idx], t3 = h3[idx];
                acc[v].x += t0.x * n0; acc[v].y += t0.y * n0;
                acc[v].z += t0.z * n0; acc[v].w += t0.w * n0;
                acc[v].x += t1.x * n1; acc[v].y += t1.y * n1;
                acc[v].z += t1.z * n1; acc[v].w += t1.w * n1;
                acc[v].x += t2.x * n2; acc[v].y += t2.y * n2;
                acc[v].z += t2.z * n2; acc[v].w += t2.w * n2;
                acc[v].x += t3.x * n3; acc[v].y += t3.y * n3;
                acc[v].z += t3.z * n3; acc[v].w += t3.w * n3;
            }
        }
        for (; e < take; e++) {
            int   s0 = __shfl_sync(~0u, myid, e);
            float n0 = __shfl_sync(~0u, mynorm, e);
            const float4* h0 = (const float4*)(h + (size_t)s0 * C);
#pragma unroll
            for (int v = 0; v < CV; v++) {
                float4 t0 = h0[lane + 32 * v];
                acc[v].x += t0.x * n0; acc[v].y += t0.y * n0;
                acc[v].z += t0.z * n0; acc[v].w += t0.w * n0;
            }
        }
    }

    float4* op = (float4*)(outp + (size_t)node * C);
#pragma unroll
    for (int v = 0; v < CV; v++) {
        const float4 b = ((const float4*)bias)[lane + 32 * v];
        float4 o = acc[v];
        o.x += b.x; o.y += b.y; o.z += b.z; o.w += b.w;
        if (RELU) {
            o.x = fmaxf(o.x, 0.f); o.y = fmaxf(o.y, 0.f);
            o.z = fmaxf(o.z, 0.f); o.w = fmaxf(o.w, 0.f);
        }
        op[lane + 32 * v] = o;
    }
}

// ---------------- launch ----------------------------------------------------
extern "C" void kernel_launch(void* const* d_in, const int* in_sizes, int n_in,
                              void* d_out, int out_size) {
    const float* x  = (const float*)d_in[0];
    const int*   ei = (const int*)d_in[1];     // int32: JAX x64 disabled
    const float* W1 = (const float*)d_in[2];
    const float* b1 = (const float*)d_in[3];
    const float* W2 = (const float*)d_in[4];
    const float* b2 = (const float*)d_in[5];
    float* out = (float*)d_out;

    const int* src = ei;
    const int* dst = ei + N_EDGES;

    float *g_h_p, *g_agg_p, *g_h2_p;
    cudaGetSymbolAddress((void**)&g_h_p,   g_h);
    cudaGetSymbolAddress((void**)&g_agg_p, g_agg);
    cudaGetSymbolAddress((void**)&g_h2_p,  g_h2);

    const int gemm_smem = sizeof(GemmSmem);           // ~69 KB
    static bool attr_set = false;
    if (!attr_set) {
        cudaFuncSetAttribute(tf32_gemm_kernel,
                             cudaFuncAttributeMaxDynamicSharedMemorySize, gemm_smem);
        attr_set = true;
    }

    // 1) CSR build + dinv
    zero_cnt_kernel<<<(N_NODES + 255) / 256, 256>>>();
    deg_count_kernel<<<(N_EDGES + 255) / 256, 256>>>(dst);
    deg_finalize_kernel<<<(N_NODES + 255) / 256, 256>>>();
    scanA_kernel<<<SCAN_NBLK, SCAN_B>>>();
    scanB_kernel<<<1, SCAN_B>>>();
    scanC_kernel<<<SCAN_NBLK, SCAN_B>>>();
    fill_kernel<<<(N_EDGES + 255) / 256, 256>>>(src, dst);

    // 2) h = x @ W1
    {
        dim3 grid((N_NODES + 127) / 128, H1 / 128);
        tf32_gemm_kernel<<<grid, 256, gemm_smem>>>(x, W1, g_h_p, N_NODES, H1, NFEAT);
    }

    // 3) h1 = relu(aggregate(h) + b1)
    gather_kernel<H1, true><<<(N_NODES * 32 + 255) / 256, 256>>>(g_h_p, g_agg_p, b1);

    // 4) h2 = h1 @ W2
    {
        dim3 grid((N_NODES + 127) / 128, H2 / 128);
        tf32_gemm_kernel<<<grid, 256, gemm_smem>>>(g_agg_p, W2, g_h2_p, N_NODES, H2, H1);
    }

    // 5) out = aggregate(h2) + b2
    gather_kernel<H2, false><<<(N_NODES * 32 + 255) / 256, 256>>>(g_h2_p, out, b2);
}

// round 16
// speedup vs baseline: 1.1328x; 1.1328x over previous
#include <cuda_runtime.h>
#include <cstdint>

#define N_NODES 50000
#define N_EDGES 800000
#define NFEAT   512
#define H1      256
#define H2      128
#define SCAN_B  256
#define SCAN_NBLK ((N_NODES + SCAN_B - 1) / SCAN_B)   // 196

// ---------------- scratch (device globals; no allocation allowed) ----------
__device__ float g_dinv[N_NODES];
__device__ int   g_cnt [N_NODES];
__device__ int   g_off [N_NODES];
__device__ int   g_cur [N_NODES];
__device__ int   g_csr_src[N_EDGES];
__device__ int   g_blksum[SCAN_NBLK];
__device__ float g_h  [N_NODES * H1];
__device__ float g_agg[N_NODES * H1];      // rna-rounded relu(aggregate)
__device__ float g_h2 [N_NODES * H2];
__device__ float g_w2r[H1 * H2];           // rna-rounded W2

// ---------------- helpers ---------------------------------------------------
__device__ __forceinline__ float tf32r(float x) {
    float y; asm("cvt.rna.tf32.f32 %0, %1;" : "=f"(y) : "f"(x));
    return y;
}
__device__ __forceinline__ uint32_t tf32u(float x) {
    return __float_as_uint(tf32r(x));
}
__device__ __forceinline__ void mma_tf32(float c[4], const uint32_t a[4],
                                         const uint32_t b[2]) {
    asm volatile(
        "mma.sync.aligned.m16n8k8.row.col.f32.tf32.tf32.f32 "
        "{%0,%1,%2,%3}, {%4,%5,%6,%7}, {%8,%9}, {%0,%1,%2,%3};"
        : "+f"(c[0]), "+f"(c[1]), "+f"(c[2]), "+f"(c[3])
        : "r"(a[0]), "r"(a[1]), "r"(a[2]), "r"(a[3]), "r"(b[0]), "r"(b[1]));
}
__device__ __forceinline__ void cp_async16(void* smem, const void* gmem, bool valid) {
    uint32_t s = (uint32_t)__cvta_generic_to_shared(smem);
    int sz = valid ? 16 : 0;
    asm volatile("cp.async.cg.shared.global [%0], [%1], 16, %2;"
                 :: "r"(s), "l"(gmem), "r"(sz));
}
#define CP_COMMIT() asm volatile("cp.async.commit_group;")
#define CP_WAIT1()  asm volatile("cp.async.wait_group 1;")
#define CP_WAIT0()  asm volatile("cp.async.wait_group 0;")

// ---------------- CSR build --------------------------------------------------
__global__ void zero_cnt_kernel() {
    int i = blockIdx.x * blockDim.x + threadIdx.x;
    if (i < N_NODES) g_cnt[i] = 0;
}
__global__ void deg_count_kernel(const int* __restrict__ dst) {
    int e = blockIdx.x * blockDim.x + threadIdx.x;
    if (e < N_EDGES) atomicAdd(&g_cnt[dst[e]], 1);
}
__global__ void deg_finalize_kernel() {
    int i = blockIdx.x * blockDim.x + threadIdx.x;
    if (i < N_NODES) g_dinv[i] = rsqrtf((float)g_cnt[i] + 1.0f);  // +1 self-loop
}
__global__ __launch_bounds__(SCAN_B)
void scanA_kernel() {
    __shared__ int sh[SCAN_B / 32];
    int idx = blockIdx.x * SCAN_B + threadIdx.x;
    int v = (idx < N_NODES) ? g_cnt[idx] : 0;
#pragma unroll
    for (int d = 16; d > 0; d >>= 1) v += __shfl_down_sync(~0u, v, d);
    if ((threadIdx.x & 31) == 0) sh[threadIdx.x >> 5] = v;
    __syncthreads();
    if (threadIdx.x < SCAN_B / 32) {
        int s = sh[threadIdx.x];
#pragma unroll
        for (int d = SCAN_B / 64; d > 0; d >>= 1) s += __shfl_down_sync(~0u, s, d);
        if (threadIdx.x == 0) g_blksum[blockIdx.x] = s;
    }
}
__global__ __launch_bounds__(SCAN_B)
void scanB_kernel() {
    __shared__ int sh[SCAN_B];
    int t = threadIdx.x;
    int v = (t < SCAN_NBLK) ? g_blksum[t] : 0;
    sh[t] = v;
    __syncthreads();
    for (int d = 1; d < SCAN_B; d <<= 1) {
        int u = (t >= d) ? sh[t - d] : 0;
        __syncthreads();
        sh[t] += u;
        __syncthreads();
    }
    if (t < SCAN_NBLK) g_blksum[t] = sh[t] - v;   // exclusive
}
__global__ __launch_bounds__(SCAN_B)
void scanC_kernel() {
    __shared__ int sh[SCAN_B];
    int t = threadIdx.x;
    int idx = blockIdx.x * SCAN_B + t;
    int v = (idx < N_NODES) ? g_cnt[idx] : 0;
    sh[t] = v;
    __syncthreads();
    for (int d = 1; d < SCAN_B; d <<= 1) {
        int u = (t >= d) ? sh[t - d] : 0;
        __syncthreads();
        sh[t] += u;
        __syncthreads();
    }
    if (idx < N_NODES) {
        int off = g_blksum[blockIdx.x] + sh[t] - v;
        g_off[idx] = off;
        g_cur[idx] = off;
    }
}
__global__ void fill_kernel(const int* __restrict__ src,
                            const int* __restrict__ dst) {
    int e = blockIdx.x * blockDim.x + threadIdx.x;
    if (e >= N_EDGES) return;
    int pos = atomicAdd(&g_cur[dst[e]], 1);
    g_csr_src[pos] = src[e];
}

// ---------------- pre-round W2 to tf32-exact fp32 ----------------------------
__global__ void round_kernel(const float* __restrict__ in,
                             float* __restrict__ out, int n) {
    int i = blockIdx.x * blockDim.x + threadIdx.x;
    if (i < n) out[i] = tf32r(in[i]);
}

// ---------------- tf32 tensor GEMM (cp.async 2-stage pipeline) --------------
#define AS_LD 36
#define BS_LD 132
struct GemmSmem {
    float As[2][128][AS_LD];
    float Bs[2][32][BS_LD];
};

template <bool CONV_A, bool CONV_B>
__global__ __launch_bounds__(256, 2)
void tf32_gemm_kernel(const float* __restrict__ A, const float* __restrict__ B,
                      float* __restrict__ C, int M, int N, int K) {
    extern __shared__ char smem_raw[];
    GemmSmem& sm = *reinterpret_cast<GemmSmem*>(smem_raw);

    int tid  = threadIdx.x;
    int m0   = blockIdx.x * 128;
    int n0   = blockIdx.y * 128;
    int wid  = tid >> 5;
    int lane = tid & 31;
    int wm = (wid & 1) * 64;
    int wn = (wid >> 1) * 32;
    int lq = lane >> 2;
    int lr = lane & 3;

    float c[4][4][4];
#pragma unroll
    for (int i = 0; i < 4; i++)
#pragma unroll
        for (int j = 0; j < 4; j++)
#pragma unroll
            for (int r = 0; r < 4; r++) c[i][j][r] = 0.0f;

    int a_r = tid >> 3;
    int a_c = (tid & 7) * 4;
    int b_r = tid >> 5;
    int b_c = (tid & 31) * 4;

    auto issue_tile = [&](int k0, int buf) {
#pragma unroll
        for (int p = 0; p < 4; p++) {
            int r = a_r + p * 32;
            bool valid = (m0 + r) < M;
            const float* gp = A + (size_t)(valid ? (m0 + r) : 0) * K + k0 + a_c;
            cp_async16(&sm.As[buf][r][a_c], gp, valid);
        }
#pragma unroll
        for (int p = 0; p < 4; p++) {
            int r = b_r + p * 8;
            cp_async16(&sm.Bs[buf][r][b_c], B + (size_t)(k0 + r) * N + n0 + b_c, true);
        }
    };

    const int nk = K / 32;
    issue_tile(0, 0);
    CP_COMMIT();

    for (int it = 0; it < nk; it++) {
        if (it + 1 < nk) {
            issue_tile((it + 1) * 32, (it + 1) & 1);
            CP_COMMIT();
            CP_WAIT1();
        } else {
            CP_WAIT0();
        }
        __syncthreads();

        int buf = it & 1;
#pragma unroll
        for (int kk = 0; kk < 4; kk++) {
            int k = kk * 8;
            uint32_t a[4][4], b[4][2];
#pragma unroll
            for (int i = 0; i < 4; i++) {
                int r = wm + i * 16 + lq;
                if (CONV_A) {
                    a[i][0] = tf32u(sm.As[buf][r    ][k + lr    ]);
                    a[i][1] = tf32u(sm.As[buf][r + 8][k + lr    ]);
                    a[i][2] = tf32u(sm.As[buf][r    ][k + lr + 4]);
                    a[i][3] = tf32u(sm.As[buf][r + 8][k + lr + 4]);
                } else {
                    a[i][0] = __float_as_uint(sm.As[buf][r    ][k + lr    ]);
                    a[i][1] = __float_as_uint(sm.As[buf][r + 8][k + lr    ]);
                    a[i][2] = __float_as_uint(sm.As[buf][r    ][k + lr + 4]);
                    a[i][3] = __float_as_uint(sm.As[buf][r + 8][k + lr + 4]);
                }
            }
#pragma unroll
            for (int j = 0; j < 4; j++) {
                int cc = wn + j * 8 + lq;
                if (CONV_B) {
                    b[j][0] = tf32u(sm.Bs[buf][k + lr    ][cc]);
                    b[j][1] = tf32u(sm.Bs[buf][k + lr + 4][cc]);
                } else {
                    b[j][0] = __float_as_uint(sm.Bs[buf][k + lr    ][cc]);
                    b[j][1] = __float_as_uint(sm.Bs[buf][k + lr + 4][cc]);
                }
            }
#pragma unroll
            for (int i = 0; i < 4; i++)
#pragma unroll
                for (int j = 0; j < 4; j++)
                    mma_tf32(c[i][j], a[i], b[j]);
        }
        __syncthreads();
    }

#pragma unroll
    for (int i = 0; i < 4; i++) {
        int r0 = m0 + wm + i * 16 + lq;
        int r1 = r0 + 8;
#pragma unroll
        for (int j = 0; j < 4; j++) {
            int col = n0 + wn + j * 8 + 2 * lr;
            if (r0 < M)
                *(float2*)(C + (size_t)r0 * N + col) =
                    make_float2(c[i][j][0], c[i][j][1]);
            if (r1 < M)
                *(float2*)(C + (size_t)r1 * N + col) =
                    make_float2(c[i][j][2], c[i][j][3]);
        }
    }
}

// ---------------- CSR gather (R9 style, unroll-4) ----------------------------
template <int C, bool RELU, bool ROUND_OUT>
__global__ void gather_kernel(const float* __restrict__ h,
                              float* __restrict__ outp,
                              const float* __restrict__ bias) {
    int node = (blockIdx.x * blockDim.x + threadIdx.x) >> 5;
    int lane = threadIdx.x & 31;
    if (node >= N_NODES) return;
    const int CV = C / 128;            // float4 per lane

    float dd = g_dinv[node];
    float w  = dd * dd;

    float4 acc[CV];
    const float4* hd = (const float4*)(h + (size_t)node * C);
#pragma unroll
    for (int v = 0; v < CV; v++) {
        float4 t = hd[lane + 32 * v];
        acc[v] = make_float4(t.x * w, t.y * w, t.z * w, t.w * w);
    }

    int j   = g_off[node];
    int end = j + g_cnt[node];

    for (; j + 3 < end; j += 4) {
        int s0 = g_csr_src[j],     s1 = g_csr_src[j + 1];
        int s2 = g_csr_src[j + 2], s3 = g_csr_src[j + 3];
        float n0 = g_dinv[s0] * dd, n1 = g_dinv[s1] * dd;
        float n2 = g_dinv[s2] * dd, n3 = g_dinv[s3] * dd;
        const float4* h0 = (const float4*)(h + (size_t)s0 * C);
        const float4* h1 = (const float4*)(h + (size_t)s1 * C);
        const float4* h2 = (const float4*)(h + (size_t)s2 * C);
        const float4* h3 = (const float4*)(h + (size_t)s3 * C);
#pragma unroll
        for (int v = 0; v < CV; v++) {
            int idx = lane + 32 * v;
            float4 t0 = h0[idx], t1 = h1[idx], t2 = h2[idx], t3 = h3[idx];
            acc[v].x += t0.x * n0; acc[v].y += t0.y * n0;
            acc[v].z += t0.z * n0; acc[v].w += t0.w * n0;
            acc[v].x += t1.x * n1; acc[v].y += t1.y * n1;
            acc[v].z += t1.z * n1; acc[v].w += t1.w * n1;
            acc[v].x += t2.x * n2; acc[v].y += t2.y * n2;
            acc[v].z += t2.z * n2; acc[v].w += t2.w * n2;
            acc[v].x += t3.x * n3; acc[v].y += t3.y * n3;
            acc[v].z += t3.z * n3; acc[v].w += t3.w * n3;
        }
    }
    for (; j < end; j++) {
        int s0 = g_csr_src[j];
        float n0 = g_dinv[s0] * dd;
        const float4* h0 = (const float4*)(h + (size_t)s0 * C);
#pragma unroll
        for (int v = 0; v < CV; v++) {
            float4 t0 = h0[lane + 32 * v];
            acc[v].x += t0.x * n0; acc[v].y += t0.y * n0;
            acc[v].z += t0.z * n0; acc[v].w += t0.w * n0;
        }
    }

    float4* op = (float4*)(outp + (size_t)node * C);
#pragma unroll
    for (int v = 0; v < CV; v++) {
        const float4 b = ((const float4*)bias)[lane + 32 * v];
        float4 o = acc[v];
        o.x += b.x; o.y += b.y; o.z += b.z; o.w += b.w;
        if (RELU) {
            o.x = fmaxf(o.x, 0.f); o.y = fmaxf(o.y, 0.f);
            o.z = fmaxf(o.z, 0.f); o.w = fmaxf(o.w, 0.f);
        }
        if (ROUND_OUT) {
            o.x = tf32r(o.x); o.y = tf32r(o.y);
            o.z = tf32r(o.z); o.w = tf32r(o.w);
        }
        op[lane + 32 * v] = o;
    }
}

// ---------------- launch ----------------------------------------------------
extern "C" void kernel_launch(void* const* d_in, const int* in_sizes, int n_in,
                              void* d_out, int out_size) {
    const float* x  = (const float*)d_in[0];
    const int*   ei = (const int*)d_in[1];     // int32: JAX x64 disabled
    const float* W1 = (const float*)d_in[2];
    const float* b1 = (const float*)d_in[3];
    const float* W2 = (const float*)d_in[4];
    const float* b2 = (const float*)d_in[5];
    float* out = (float*)d_out;

    const int* src = ei;
    const int* dst = ei + N_EDGES;

    float *g_h_p, *g_agg_p, *g_h2_p, *g_w2r_p;
    cudaGetSymbolAddress((void**)&g_h_p,   g_h);
    cudaGetSymbolAddress((void**)&g_agg_p, g_agg);
    cudaGetSymbolAddress((void**)&g_h2_p,  g_h2);
    cudaGetSymbolAddress((void**)&g_w2r_p, g_w2r);

    const int gemm_smem = sizeof(GemmSmem);           // ~69 KB
    static bool init_done = false;
    static cudaStream_t s2;
    static cudaEvent_t ev_fork, ev_join;
    if (!init_done) {
        cudaFuncSetAttribute(tf32_gemm_kernel<true, true>,
                             cudaFuncAttributeMaxDynamicSharedMemorySize, gemm_smem);
        cudaFuncSetAttribute(tf32_gemm_kernel<false, false>,
                             cudaFuncAttributeMaxDynamicSharedMemorySize, gemm_smem);
        cudaStreamCreateWithFlags(&s2, cudaStreamNonBlocking);
        cudaEventCreateWithFlags(&ev_fork, cudaEventDisableTiming);
        cudaEventCreateWithFlags(&ev_join, cudaEventDisableTiming);
        init_done = true;
    }

    // fork: CSR build + W2 pre-round on side stream; GEMM1 on main stream.
    // GEMM1 consumes ONLY x and raw W1 — no dependency on the side stream.
    cudaEventRecord(ev_fork, 0);
    cudaStreamWaitEvent(s2, ev_fork, 0);

    // --- side stream: CSR build + dinv + W2 round ---
    zero_cnt_kernel<<<(N_NODES + 255) / 256, 256, 0, s2>>>();
    deg_count_kernel<<<(N_EDGES + 255) / 256, 256, 0, s2>>>(dst);
    deg_finalize_kernel<<<(N_NODES + 255) / 256, 256, 0, s2>>>();
    scanA_kernel<<<SCAN_NBLK, SCAN_B, 0, s2>>>();
    scanB_kernel<<<1, SCAN_B, 0, s2>>>();
    scanC_kernel<<<SCAN_NBLK, SCAN_B, 0, s2>>>();
    fill_kernel<<<(N_EDGES + 255) / 256, 256, 0, s2>>>(src, dst);
    round_kernel<<<(H1 * H2 + 255) / 256, 256, 0, s2>>>(W2, g_w2r_p, H1 * H2);
    cudaEventRecord(ev_join, s2);

    // --- main stream: h = x @ W1 (both operands cvt'd in-loop, raw inputs) ---
    {
        dim3 grid((N_NODES + 127) / 128, H1 / 128);
        tf32_gemm_kernel<true, true><<<grid, 256, gemm_smem>>>(
            x, W1, g_h_p, N_NODES, H1, NFEAT);
    }

    // join: gather1 needs CSR + dinv (and precedes GEMM2, which needs g_w2r)
    cudaStreamWaitEvent(0, ev_join, 0);

    // h1 = relu(aggregate(h) + b1), stored tf32-rounded
    gather_kernel<H1, true, true><<<(N_NODES * 32 + 255) / 256, 256>>>(
        g_h_p, g_agg_p, b1);

    // h2 = h1 @ W2 (zero in-loop cvt: both inputs tf32-exact)
    {
        dim3 grid((N_NODES + 127) / 128, H2 / 128);
        tf32_gemm_kernel<false, false><<<grid, 256, gemm_smem>>>(
            g_agg_p, g_w2r_p, g_h2_p, N_NODES, H2, H1);
    }

    // out = aggregate(h2) + b2
    gather_kernel<H2, false, false><<<(N_NODES * 32 + 255) / 256, 256>>>(
        g_h2_p, out, b2);
}